// round 15
// baseline (speedup 1.0000x reference)
#include <cuda_runtime.h>
#include <cuda_fp16.h>
#include <math.h>
#include <stdint.h>

#define BATCH 32
#define SEQ   2048
#define DQ    1024
#define DV    1024
#define UN    1024
#define ROWS  (BATCH * SEQ)

#define BM 128
#define BN 128
#define CHUNK_A 8192                  // per 32-k sub-chunk
#define CHUNK_B 8192
#define NCHUNK (DV / 32)              // 32 sub-chunks
#define NSTEP  16                     // stages consumed (2 sub-chunks each)
#define STAGE_BYTES 32768             // A 16K | B 16K
#define NSTAGE 3
#define SMEM_BYTES (1024 + NSTAGE * STAGE_BYTES)   // 99328
#define NCTX 64
#define NRB (ROWS / BM)               // 512 row-blocks
#define NSCHUNK (ROWS / 256)          // 256 score chunks

// ---------------- device scratch ------------------------------------------
__device__ unsigned char g_at[(size_t)NRB * NCHUNK * CHUNK_A];  // 128MB
__device__ unsigned char g_bt[(size_t)(UN / BN) * NCHUNK * CHUNK_B];    // 2MB
__device__ float g_projq[BATCH * UN];
__device__ float g_spart[(size_t)ROWS * 8];
__device__ float g_score[ROWS];
__device__ float g_stats[NSCHUNK * 2];       // per 256-row chunk: max, expsum
__device__ float g_cpart[(size_t)NCTX * BATCH * DV];
__device__ int   g_flag[NRB];                // row-block conversion flags
__device__ unsigned g_cnt_sc[NSCHUNK];       // score-chunk arrival counters
__device__ unsigned g_cnt_ctx[BATCH];        // ctx per-batch arrival counters

// ---------------- helpers ---------------------------------------------------
__device__ __forceinline__ uint32_t smem_u32(const void* p) {
    uint32_t a;
    asm("{ .reg .u64 t; cvta.to.shared.u64 t, %1; cvt.u32.u64 %0, t; }" : "=r"(a) : "l"(p));
    return a;
}
#define MBARRIER_INIT(addr, cnt) \
    asm volatile("mbarrier.init.shared.b64 [%0], %1;" :: "r"((uint32_t)(addr)), "r"((uint32_t)(cnt)) : "memory")
#define MBARRIER_ARRIVE(addr) \
    asm volatile("mbarrier.arrive.shared.b64 _, [%0];" :: "r"((uint32_t)(addr)) : "memory")
#define MBARRIER_EXPECT_TX(addr, tx) \
    asm volatile("mbarrier.arrive.expect_tx.shared.b64 _, [%0], %1;" :: "r"((uint32_t)(addr)), "r"((uint32_t)(tx)) : "memory")
#define MBARRIER_WAIT(addr, ph) do { \
    uint32_t _m = (uint32_t)(addr), _p = (uint32_t)(ph), _d; \
    asm volatile("{\n\t.reg .pred p;\n\t" \
        "mbarrier.try_wait.parity.acquire.cta.shared::cta.b64 p, [%1], %2;\n\t" \
        "selp.b32 %0, 1, 0, p;\n\t}" : "=r"(_d) : "r"(_m), "r"(_p) : "memory"); \
    if (!_d) { \
        asm volatile("{\n\t.reg .pred P1;\n\t" \
            "WL_%=:\n\t" \
            "mbarrier.try_wait.parity.acquire.cta.shared::cta.b64 P1, [%0], %1, 0x989680;\n\t" \
            "@P1 bra.uni WD_%=;\n\t" \
            "bra.uni WL_%=;\n\t" \
            "WD_%=:\n\t}" :: "r"(_m), "r"(_p) : "memory"); \
    } \
} while (0)
#define MBARRIER_WAIT_RELAXED(addr, ph) do { \
    uint32_t _m = (uint32_t)(addr), _p = (uint32_t)(ph), _d; \
    asm volatile("{\n\t.reg .pred p;\n\t" \
        "mbarrier.try_wait.parity.relaxed.cta.shared::cta.b64 p, [%1], %2;\n\t" \
        "selp.b32 %0, 1, 0, p;\n\t}" : "=r"(_d) : "r"(_m), "r"(_p) : "memory"); \
    if (!_d) { \
        asm volatile("{\n\t.reg .pred P1;\n\t" \
            "WL_%=:\n\t" \
            "mbarrier.try_wait.parity.relaxed.cta.shared::cta.b64 P1, [%0], %1, 0x989680;\n\t" \
            "@P1 bra.uni WD_%=;\n\t" \
            "bra.uni WL_%=;\n\t" \
            "WD_%=:\n\t}" :: "r"(_m), "r"(_p) : "memory"); \
    } \
} while (0)
#define FENCE_PROXY_ASYNC_GEN() asm volatile("fence.proxy.async;" ::: "memory")
__device__ __forceinline__ void cp_bulk(uint32_t dst, const void* src, uint32_t bytes,
                                        uint32_t mbar) {
    asm volatile("cp.async.bulk.shared::cta.global.mbarrier::complete_tx::bytes "
                 "[%0], [%1], %2, [%3];"
                 :: "r"(dst), "l"(src), "r"(bytes), "r"(mbar) : "memory");
}
#define LDSM_X4(R, addr) \
    asm volatile("ldmatrix.sync.aligned.m8n8.x4.shared.b16 {%0,%1,%2,%3}, [%4];" \
        : "=r"((R)[0]), "=r"((R)[1]), "=r"((R)[2]), "=r"((R)[3]) : "r"(addr))
#define MMA16816(C, A, B0, B1) \
    asm volatile("mma.sync.aligned.m16n8k16.row.col.f32.f16.f16.f32 " \
        "{%0,%1,%2,%3},{%4,%5,%6,%7},{%8,%9},{%0,%1,%2,%3};" \
        : "+f"((C)[0]), "+f"((C)[1]), "+f"((C)[2]), "+f"((C)[3]) \
        : "r"((A)[0]), "r"((A)[1]), "r"((A)[2]), "r"((A)[3]), "r"(B0), "r"(B1))

// SW64 swizzle: 64B rows; 16B chunk c of row r -> c ^ ((r>>1)&3)
__device__ __forceinline__ uint32_t sw64_off(int row, int c) {
    return (uint32_t)(row * 64 + ((c ^ ((row >> 1) & 3)) << 4));
}

// MUFU tanh for the score epilogue
__device__ __forceinline__ float tanh_mufu(float x) {
    float ax = fabsf(x);
    float e  = __expf(2.0f * ax);
    float t  = 1.0f - __fdividef(2.0f, e + 1.0f);
    return copysignf(t, x);
}

// ---------------------------------------------------------------------------
// prep: clear flags/counters | W1^T split | proj_q
// ---------------------------------------------------------------------------
#define PREP_W1T_BLOCKS   1024
#define PREP_PROJQ_BLOCKS 128
#define PREP_BLOCKS (1 + PREP_W1T_BLOCKS + PREP_PROJQ_BLOCKS)

__global__ void prep_kernel(const float* __restrict__ W1,
                            const float* __restrict__ q,
                            const float* __restrict__ W2,
                            const float* __restrict__ b2) {
    const int bid = blockIdx.x;
    const int tid = threadIdx.x;

    if (bid == 0) {
        if (tid < NRB) g_flag[tid] = 0;
        if (tid + 256 < NRB) g_flag[tid + 256] = 0;
        if (tid < NSCHUNK) g_cnt_sc[tid] = 0;
        if (tid < BATCH) g_cnt_ctx[tid] = 0;
        __threadfence();
    } else if (bid <= PREP_W1T_BLOCKS) {
        __shared__ float t[32][33];
        const int b2d = bid - 1;
        const int bx = (b2d & 31) * 32, by = (b2d >> 5) * 32;  // bx: u, by: k
        const int tx = tid & 31, ty = tid >> 5;
#pragma unroll
        for (int rr = 0; rr < 4; ++rr)
            t[ty + 8 * rr][tx] = W1[(size_t)(by + ty + 8 * rr) * UN + bx + tx];
        __syncthreads();
        const int u = bx + tx, k0 = by + ty * 4;
        float4 x;
        x.x = t[ty * 4 + 0][tx]; x.y = t[ty * 4 + 1][tx];
        x.z = t[ty * 4 + 2][tx]; x.w = t[ty * 4 + 3][tx];
        const int ut = u >> 7, r = u & 127;
        const int ch = k0 >> 5, ci = k0 & 31;
        const int sw = (ci >> 3) ^ ((r >> 1) & 3);
        unsigned char* base = g_bt + ((size_t)(ut * NCHUNK + ch) * CHUNK_B)
                                   + r * 64 + sw * 16 + (ci & 7) * 2;
        __half2 a = __halves2half2(__float2half_rn(x.x), __float2half_rn(x.y));
        __half2 b = __halves2half2(__float2half_rn(x.z), __float2half_rn(x.w));
        uint2 hi;
        hi.x = *(uint32_t*)&a; hi.y = *(uint32_t*)&b;
        *(uint2*)base = hi;
    } else {
        const int b3 = bid - 1 - PREP_W1T_BLOCKS;
        const int u = (b3 & 3) * 256 + tid;
        const int b = b3 >> 2;
        const float* qb = q + b * DQ;
        float acc = b2[u];
#pragma unroll 8
        for (int d = 0; d < DQ; ++d)
            acc = fmaf(qb[d], W2[(size_t)d * UN + u], acc);
        g_projq[b * UN + u] = acc;
    }
}

// ---------------------------------------------------------------------------
// score: fused values-split + fp16 HMMA GEMM + last-CTA softmax stats.
// ---------------------------------------------------------------------------
__global__ __launch_bounds__(288, 2) void score_kernel(
    const float* __restrict__ vsrc,
    const float* __restrict__ b1g, const float* __restrict__ Vv) {

    extern __shared__ char smem[];
    const uint32_t sb    = smem_u32(smem);
    const uint32_t FULLB = sb;
    const uint32_t EMPTB = sb + 24;
    const uint32_t SDATA = sb + 1024;
    __shared__ int s_last;

    const int tid = threadIdx.x, wid = tid >> 5, lane = tid & 31;
    const int bid = blockIdx.x;
    int bx, by;
    if (bid < NRB) { bx = 0; by = bid; }
    else { const int x = bid - NRB; by = x / 7; bx = 1 + x % 7; }
    const int u0   = bx * BN;
    const int row0 = by * BM;
    const int b    = row0 >> 11;
    const int warp_m = wid & 1, warp_n = wid >> 1;

    const unsigned char* gA = g_at + (size_t)by * (NCHUNK * CHUNK_A);
    const unsigned char* gB = g_bt + (size_t)bx * (NCHUNK * CHUNK_B);

    if (tid == 0) {
#pragma unroll
        for (int st = 0; st < NSTAGE; ++st) {
            MBARRIER_INIT(FULLB + st * 8, 1);
            MBARRIER_INIT(EMPTB + st * 8, 8);
        }
    }
    __syncthreads();

    if (bx == 0) {
        // -------- convert own row-block: fp32 values -> swizzled fp16 -------
        if (wid < 8) {
            const float* src = vsrc + (size_t)by * (BM * DV);
            unsigned char* dstb = g_at + (size_t)by * (NCHUNK * CHUNK_A);
#pragma unroll 4
            for (int it = 0; it < 64; ++it) {
                const int il = it * 2048 + tid * 8;
                const float4 x0 = *(const float4*)(src + il);
                const float4 x1 = *(const float4*)(src + il + 4);
                const int row = il >> 10, col = il & 1023;
                const int ch = col >> 5, ci = col & 31;
                const int sw = (ci >> 3) ^ ((row >> 1) & 3);
                unsigned char* p = dstb + (size_t)ch * CHUNK_A + row * 64 + sw * 16;
                __half2 a0 = __halves2half2(__float2half_rn(x0.x), __float2half_rn(x0.y));
                __half2 a1 = __halves2half2(__float2half_rn(x0.z), __float2half_rn(x0.w));
                __half2 a2 = __halves2half2(__float2half_rn(x1.x), __float2half_rn(x1.y));
                __half2 a3 = __halves2half2(__float2half_rn(x1.z), __float2half_rn(x1.w));
                uint4 out;
                out.x = *(uint32_t*)&a0; out.y = *(uint32_t*)&a1;
                out.z = *(uint32_t*)&a2; out.w = *(uint32_t*)&a3;
                *(uint4*)p = out;
            }
        }
        __syncthreads();
        if (tid == 0) {
            asm volatile("membar.gl;" ::: "memory");
            asm volatile("st.release.gpu.global.b32 [%0], %1;"
                         :: "l"(g_flag + by), "r"(1) : "memory");
        }
    }

    if (wid == 8) {
        // ---------------- producer warp -------------------------------------
        if (lane == 0) {
            if (bx != 0) {
                int f;
                do {
                    asm volatile("ld.acquire.gpu.global.b32 %0, [%1];"
                                 : "=r"(f) : "l"(g_flag + by) : "memory");
                    if (!f) __nanosleep(256);
                } while (!f);
            }
            FENCE_PROXY_ASYNC_GEN();
            int st = 0, r = 0;
            for (int t = 0; t < NSTEP; ++t) {
                if (t >= NSTAGE) MBARRIER_WAIT_RELAXED(EMPTB + st * 8, (r - 1) & 1);
                const uint32_t dst = SDATA + st * STAGE_BYTES;
                MBARRIER_EXPECT_TX(FULLB + st * 8, STAGE_BYTES);
                cp_bulk(dst,         gA + (size_t)t * 16384, 16384, FULLB + st * 8);
                cp_bulk(dst + 16384, gB + (size_t)t * 16384, 16384, FULLB + st * 8);
                if (++st == NSTAGE) { st = 0; ++r; }
            }
        }
    } else {
        // ---------------- compute warps -------------------------------------
        const int lr = lane & 15, lh = lane >> 4;
        uint32_t aoff[4], boff[2];
#pragma unroll
        for (int mt = 0; mt < 4; ++mt)
            aoff[mt] = sw64_off(warp_m * 64 + mt * 16 + lr, lh);
#pragma unroll
        for (int bt = 0; bt < 2; ++bt)
            boff[bt] = sw64_off(warp_n * 32 + bt * 16 + lr, lh);

        float acc[4][4][4];
#pragma unroll
        for (int i = 0; i < 4; ++i)
#pragma unroll
            for (int j = 0; j < 4; ++j)
#pragma unroll
                for (int k = 0; k < 4; ++k) acc[i][j][k] = 0.0f;

        int st = 0, rnd = 0;
        for (int s = 0; s < NSTEP; ++s) {
            const uint32_t sb_cp = SDATA + st * STAGE_BYTES;
            MBARRIER_WAIT(FULLB + st * 8, rnd & 1);

            uint32_t a[2][4][4], bh[2][4];
#pragma unroll
            for (int mt = 0; mt < 4; ++mt)
                LDSM_X4(a[0][mt], sb_cp + aoff[mt]);

#pragma unroll
            for (int k = 0; k < 4; ++k) {
                const int cur = k & 1, nxt = cur ^ 1;
                const uint32_t sub = (k >> 1) * 8192;
                const uint32_t kx  = (k & 1) << 5;
                const uint32_t abase = sb_cp + sub;
#pragma unroll
                for (int bt = 0; bt < 2; ++bt)
                    LDSM_X4(bh[bt], abase + 16384 + (boff[bt] ^ kx));
                if (k < 3) {
                    const int k2 = k + 1;
                    const uint32_t sub2 = (k2 >> 1) * 8192;
                    const uint32_t kx2  = (k2 & 1) << 5;
#pragma unroll
                    for (int mt = 0; mt < 4; ++mt)
                        LDSM_X4(a[nxt][mt], sb_cp + sub2 + (aoff[mt] ^ kx2));
                } else {
                    if (lane == 0) MBARRIER_ARRIVE(EMPTB + st * 8);
                }
#pragma unroll
                for (int mt = 0; mt < 4; ++mt)
#pragma unroll
                    for (int nt = 0; nt < 4; ++nt)
                        MMA16816(acc[mt][nt], a[cur][mt],
                                 bh[nt >> 1][nt & 1], bh[nt >> 1][(nt & 1) + 2]);
            }
            if (++st == NSTAGE) { st = 0; ++rnd; }
        }

        __syncthreads();   // joins producer sync below

        // ---------------- fused epilogue (MUFU tanh) ------------------------
        float tb[8], tv[8];
#pragma unroll
        for (int nt = 0; nt < 4; ++nt)
#pragma unroll
            for (int par = 0; par < 2; ++par) {
                const int u = u0 + warp_n * 32 + nt * 8 + (lane & 3) * 2 + par;
                tb[nt * 2 + par] = b1g[u] + g_projq[b * UN + u];
                tv[nt * 2 + par] = Vv[u];
            }

        float* red = (float*)(smem + 1024);
#pragma unroll
        for (int mt = 0; mt < 4; ++mt) {
            float s0 = 0.0f, s1 = 0.0f;
#pragma unroll
            for (int nt = 0; nt < 4; ++nt)
#pragma unroll
                for (int par = 0; par < 2; ++par) {
                    const int j = nt * 2 + par;
                    s0 = fmaf(tanh_mufu(acc[mt][nt][par]     + tb[j]), tv[j], s0);
                    s1 = fmaf(tanh_mufu(acc[mt][nt][2 + par] + tb[j]), tv[j], s1);
                }
            s0 += __shfl_xor_sync(0xffffffff, s0, 1);
            s0 += __shfl_xor_sync(0xffffffff, s0, 2);
            s1 += __shfl_xor_sync(0xffffffff, s1, 1);
            s1 += __shfl_xor_sync(0xffffffff, s1, 2);
            if ((lane & 3) == 0) {
                const int r = warp_m * 64 + mt * 16 + (lane >> 2);
                red[r * 4 + warp_n]       = s0;
                red[(r + 8) * 4 + warp_n] = s1;
            }
        }
    }
    if (wid == 8) __syncthreads();   // producer joins first barrier
    __syncthreads();                  // red[] complete
    if (tid < 128) {
        float* red = (float*)(smem + 1024);
        const float s = (red[tid * 4 + 0] + red[tid * 4 + 1]) +
                        (red[tid * 4 + 2] + red[tid * 4 + 3]);
        g_spart[(size_t)(row0 + tid) * 8 + bx] = s;
    }
    __syncthreads();                  // g_spart writes done

    // -------- last-CTA-per-chunk: fold partials + softmax stats -------------
    if (tid == 0) {
        __threadfence();
        s_last = (atomicAdd(&g_cnt_sc[by >> 1], 1u) == 15u);
    }
    __syncthreads();
    if (s_last) {
        __threadfence();
        float* red = (float*)(smem + 1024);
        const int chunk = by >> 1;
        float v = -1e30f;
        if (tid < 256) {
            const int row = chunk * 256 + tid;
            const float* p = g_spart + (size_t)row * 8;
            v = ((p[0] + p[1]) + (p[2] + p[3])) + ((p[4] + p[5]) + (p[6] + p[7]));
            g_score[row] = v;
            red[tid] = v;
        }
        __syncthreads();
        for (int s = 128; s > 0; s >>= 1) {
            if (tid < s) red[tid] = fmaxf(red[tid], red[tid + s]);
            __syncthreads();
        }
        const float m = red[0];
        __syncthreads();
        if (tid < 256) red[tid] = __expf(v - m);
        __syncthreads();
        for (int s = 128; s > 0; s >>= 1) {
            if (tid < s) red[tid] += red[tid + s];
            __syncthreads();
        }
        if (tid == 0) {
            g_stats[chunk * 2]     = m;
            g_stats[chunk * 2 + 1] = red[0];
        }
    }
}

// ---------------------------------------------------------------------------
// context partial (fused softmax finalize + last-CTA batch reduce)
// ---------------------------------------------------------------------------
__global__ void ctx_part_kernel(float* __restrict__ out_w,
                                float* __restrict__ out_c) {
    __shared__ float ws[32];
    __shared__ float part[128 * 8];
    __shared__ int s_last;
    const int sc = blockIdx.x, b = blockIdx.y, tid = threadIdx.x;

    float M = -1e30f;
#pragma unroll
    for (int c = 0; c < 8; ++c) M = fmaxf(M, g_stats[(b * 8 + c) * 2]);
    float S = 0.0f;
#pragma unroll
    for (int c = 0; c < 8; ++c)
        S += g_stats[(b * 8 + c) * 2 + 1] * __expf(g_stats[(b * 8 + c) * 2] - M);
    const float inv = 1.0f / S;

    if (tid < 32) {
        const int row = b * SEQ + sc * 32 + tid;
        const float wv = __expf(g_score[row] - M) * inv;
        ws[tid] = wv;
        out_w[row] = wv;
    }
    __syncthreads();

    const int g  = tid & 127;
    const int h  = tid >> 7;
    const int ch = g >> 2;
    const int c  = g & 3;
    const int row_base = b * SEQ + sc * 32;
    const int rb = row_base >> 7;
    const int r0 = (row_base & 127) + h * 16;
    const unsigned char* tile = g_at + ((size_t)(rb * NCHUNK + ch) * CHUNK_A);

    float acc[8];
#pragma unroll
    for (int k = 0; k < 8; ++k) acc[k] = 0.0f;
#pragma unroll
    for (int j = 0; j < 16; ++j) {
        const int r = r0 + j;
        const uint4 pk = *(const uint4*)(tile + r * 64 + ((c ^ ((r >> 1) & 3)) << 4));
        const __half2 p0 = *(const __half2*)&pk.x;
        const __half2 p1 = *(const __half2*)&pk.y;
        const __half2 p2 = *(const __half2*)&pk.z;
        const __half2 p3 = *(const __half2*)&pk.w;
        const float x = ws[h * 16 + j];
        acc[0] = fmaf(x, __low2float(p0),  acc[0]);
        acc[1] = fmaf(x, __high2float(p0), acc[1]);
        acc[2] = fmaf(x, __low2float(p1),  acc[2]);
        acc[3] = fmaf(x, __high2float(p1), acc[3]);
        acc[4] = fmaf(x, __low2float(p2),  acc[4]);
        acc[5] = fmaf(x, __high2float(p2), acc[5]);
        acc[6] = fmaf(x, __low2float(p3),  acc[6]);
        acc[7] = fmaf(x, __high2float(p3), acc[7]);
    }
    if (h == 1) {
#pragma unroll
        for (int k = 0; k < 8; ++k) part[g * 8 + k] = acc[k];
    }
    __syncthreads();
    if (h == 0) {
        float* dst = g_cpart + (size_t)(sc * BATCH + b) * DV + g * 8;
        float4 o0, o1;
        o0.x = acc[0] + part[g * 8 + 0]; o0.y = acc[1] + part[g * 8 + 1];
        o0.z = acc[2] + part[g * 8 + 2]; o0.w = acc[3] + part[g * 8 + 3];
        o1.x = acc[4] + part[g * 8 + 4]; o1.y = acc[5] + part[g * 8 + 5];
        o1.z = acc[6] + part[g * 8 + 6]; o1.w = acc[7] + part[g * 8 + 7];
        *(float4*)dst       = o0;
        *(float4*)(dst + 4) = o1;
    }
    __syncthreads();   // all g_cpart writes for this block done

    // -------- last block per batch: 64-way deterministic reduce -------------
    if (tid == 0) {
        __threadfence();
        s_last = (atomicAdd(&g_cnt_ctx[b], 1u) == (unsigned)(NCTX - 1));
    }
    __syncthreads();
    if (s_last) {
        __threadfence();
        for (int d = tid; d < DV; d += 256) {
            float s = 0.0f;
#pragma unroll 8
            for (int cc = 0; cc < NCTX; ++cc)
                s += g_cpart[(size_t)(cc * BATCH + b) * DV + d];
            out_c[b * DV + d] = s;
        }
    }
}

// ---------------------------------------------------------------------------
extern "C" void kernel_launch(void* const* d_in, const int* in_sizes, int n_in,
                              void* d_out, int out_size) {
    const float* query  = (const float*)d_in[0];
    const float* values = (const float*)d_in[1];
    const float* W1     = (const float*)d_in[2];
    const float* b1     = (const float*)d_in[3];
    const float* W2     = (const float*)d_in[4];
    const float* b2     = (const float*)d_in[5];
    const float* Vv     = (const float*)d_in[6];
    // d_in[7] = bV: cancels in softmax.

    float* out_c = (float*)d_out;
    float* out_w = out_c + BATCH * DV;

    static bool attr_set = false;
    if (!attr_set) {
        cudaFuncSetAttribute(score_kernel,
                             cudaFuncAttributeMaxDynamicSharedMemorySize, SMEM_BYTES);
        attr_set = true;
    }

    prep_kernel<<<PREP_BLOCKS, 256>>>(W1, query, W2, b2);
    score_kernel<<<4096, 288, SMEM_BYTES>>>(values, b1, Vv);
    ctx_part_kernel<<<dim3(NCTX, BATCH), 256>>>(out_w, out_c);
}

// round 16
// speedup vs baseline: 1.0555x; 1.0555x over previous
#include <cuda_runtime.h>
#include <cuda_fp16.h>
#include <math.h>
#include <stdint.h>

#define BATCH 32
#define SEQ   2048
#define DQ    1024
#define DV    1024
#define UN    1024
#define ROWS  (BATCH * SEQ)

#define BM 128
#define BN 128
#define CHUNK_A 8192                  // per 32-k sub-chunk
#define CHUNK_B 8192
#define NCHUNK (DV / 32)              // 32 sub-chunks
#define NSTEP  16                     // stages consumed (2 sub-chunks each)
#define STAGE_BYTES 32768             // A 16K | B 16K
#define NSTAGE 3
#define SMEM_BYTES (1024 + NSTAGE * STAGE_BYTES)   // 99328
#define NCTX 64
#define NRB (ROWS / BM)               // 512 row-blocks

// ---------------- device scratch ------------------------------------------
__device__ unsigned char g_at[(size_t)NRB * NCHUNK * CHUNK_A];  // 128MB
__device__ unsigned char g_bt[(size_t)(UN / BN) * NCHUNK * CHUNK_B];    // 2MB
__device__ float g_projq[BATCH * UN];
__device__ float g_spart[(size_t)ROWS * 8];
__device__ float g_score[ROWS];
__device__ float g_stats[BATCH * 8 * 2];     // per (b, chunk): max, expsum
__device__ float g_cpart[(size_t)NCTX * BATCH * DV];
__device__ int   g_flag[NRB];                // row-block conversion flags

// ---------------- helpers ---------------------------------------------------
__device__ __forceinline__ uint32_t smem_u32(const void* p) {
    uint32_t a;
    asm("{ .reg .u64 t; cvta.to.shared.u64 t, %1; cvt.u32.u64 %0, t; }" : "=r"(a) : "l"(p));
    return a;
}
#define MBARRIER_INIT(addr, cnt) \
    asm volatile("mbarrier.init.shared.b64 [%0], %1;" :: "r"((uint32_t)(addr)), "r"((uint32_t)(cnt)) : "memory")
#define MBARRIER_ARRIVE(addr) \
    asm volatile("mbarrier.arrive.shared.b64 _, [%0];" :: "r"((uint32_t)(addr)) : "memory")
#define MBARRIER_EXPECT_TX(addr, tx) \
    asm volatile("mbarrier.arrive.expect_tx.shared.b64 _, [%0], %1;" :: "r"((uint32_t)(addr)), "r"((uint32_t)(tx)) : "memory")
#define MBARRIER_WAIT(addr, ph) do { \
    uint32_t _m = (uint32_t)(addr), _p = (uint32_t)(ph), _d; \
    asm volatile("{\n\t.reg .pred p;\n\t" \
        "mbarrier.try_wait.parity.acquire.cta.shared::cta.b64 p, [%1], %2;\n\t" \
        "selp.b32 %0, 1, 0, p;\n\t}" : "=r"(_d) : "r"(_m), "r"(_p) : "memory"); \
    if (!_d) { \
        asm volatile("{\n\t.reg .pred P1;\n\t" \
            "WL_%=:\n\t" \
            "mbarrier.try_wait.parity.acquire.cta.shared::cta.b64 P1, [%0], %1, 0x989680;\n\t" \
            "@P1 bra.uni WD_%=;\n\t" \
            "bra.uni WL_%=;\n\t" \
            "WD_%=:\n\t}" :: "r"(_m), "r"(_p) : "memory"); \
    } \
} while (0)
#define MBARRIER_WAIT_RELAXED(addr, ph) do { \
    uint32_t _m = (uint32_t)(addr), _p = (uint32_t)(ph), _d; \
    asm volatile("{\n\t.reg .pred p;\n\t" \
        "mbarrier.try_wait.parity.relaxed.cta.shared::cta.b64 p, [%1], %2;\n\t" \
        "selp.b32 %0, 1, 0, p;\n\t}" : "=r"(_d) : "r"(_m), "r"(_p) : "memory"); \
    if (!_d) { \
        asm volatile("{\n\t.reg .pred P1;\n\t" \
            "WL_%=:\n\t" \
            "mbarrier.try_wait.parity.relaxed.cta.shared::cta.b64 P1, [%0], %1, 0x989680;\n\t" \
            "@P1 bra.uni WD_%=;\n\t" \
            "bra.uni WL_%=;\n\t" \
            "WD_%=:\n\t}" :: "r"(_m), "r"(_p) : "memory"); \
    } \
} while (0)
#define FENCE_PROXY_ASYNC_GEN() asm volatile("fence.proxy.async;" ::: "memory")
__device__ __forceinline__ void cp_bulk(uint32_t dst, const void* src, uint32_t bytes,
                                        uint32_t mbar) {
    asm volatile("cp.async.bulk.shared::cta.global.mbarrier::complete_tx::bytes "
                 "[%0], [%1], %2, [%3];"
                 :: "r"(dst), "l"(src), "r"(bytes), "r"(mbar) : "memory");
}
#define LDSM_X4(R, addr) \
    asm volatile("ldmatrix.sync.aligned.m8n8.x4.shared.b16 {%0,%1,%2,%3}, [%4];" \
        : "=r"((R)[0]), "=r"((R)[1]), "=r"((R)[2]), "=r"((R)[3]) : "r"(addr))
#define MMA16816(C, A, B0, B1) \
    asm volatile("mma.sync.aligned.m16n8k16.row.col.f32.f16.f16.f32 " \
        "{%0,%1,%2,%3},{%4,%5,%6,%7},{%8,%9},{%0,%1,%2,%3};" \
        : "+f"((C)[0]), "+f"((C)[1]), "+f"((C)[2]), "+f"((C)[3]) \
        : "r"((A)[0]), "r"((A)[1]), "r"((A)[2]), "r"((A)[3]), "r"(B0), "r"(B1))

// SW64 swizzle: 64B rows; 16B chunk c of row r -> c ^ ((r>>1)&3)
__device__ __forceinline__ uint32_t sw64_off(int row, int c) {
    return (uint32_t)(row * 64 + ((c ^ ((row >> 1) & 3)) << 4));
}

// MUFU tanh for the score epilogue
__device__ __forceinline__ float tanh_mufu(float x) {
    float ax = fabsf(x);
    float e  = __expf(2.0f * ax);
    float t  = 1.0f - __fdividef(2.0f, e + 1.0f);
    return copysignf(t, x);
}

// ---------------------------------------------------------------------------
// prep: clear flags | W1^T split | proj_q (high-MLP version)
// ---------------------------------------------------------------------------
#define PREP_W1T_BLOCKS   1024
#define PREP_PROJQ_BLOCKS 128
#define PREP_BLOCKS (1 + PREP_W1T_BLOCKS + PREP_PROJQ_BLOCKS)

__global__ void prep_kernel(const float* __restrict__ W1,
                            const float* __restrict__ q,
                            const float* __restrict__ W2,
                            const float* __restrict__ b2) {
    const int bid = blockIdx.x;
    const int tid = threadIdx.x;

    if (bid == 0) {
        if (tid < NRB) g_flag[tid] = 0;
        if (tid + 256 < NRB) g_flag[tid + 256] = 0;
        __threadfence();
    } else if (bid <= PREP_W1T_BLOCKS) {
        __shared__ float t[32][33];
        const int b2d = bid - 1;
        const int bx = (b2d & 31) * 32, by = (b2d >> 5) * 32;  // bx: u, by: k
        const int tx = tid & 31, ty = tid >> 5;
#pragma unroll
        for (int rr = 0; rr < 4; ++rr)
            t[ty + 8 * rr][tx] = W1[(size_t)(by + ty + 8 * rr) * UN + bx + tx];
        __syncthreads();
        const int u = bx + tx, k0 = by + ty * 4;
        float4 x;
        x.x = t[ty * 4 + 0][tx]; x.y = t[ty * 4 + 1][tx];
        x.z = t[ty * 4 + 2][tx]; x.w = t[ty * 4 + 3][tx];
        const int ut = u >> 7, r = u & 127;
        const int ch = k0 >> 5, ci = k0 & 31;
        const int sw = (ci >> 3) ^ ((r >> 1) & 3);
        unsigned char* base = g_bt + ((size_t)(ut * NCHUNK + ch) * CHUNK_B)
                                   + r * 64 + sw * 16 + (ci & 7) * 2;
        __half2 a = __halves2half2(__float2half_rn(x.x), __float2half_rn(x.y));
        __half2 b = __halves2half2(__float2half_rn(x.z), __float2half_rn(x.w));
        uint2 hi;
        hi.x = *(uint32_t*)&a; hi.y = *(uint32_t*)&b;
        *(uint2*)base = hi;
    } else {
        // ---- proj_q with 4 independent accumulators + deep unroll ----------
        const int b3 = bid - 1 - PREP_W1T_BLOCKS;
        const int u = (b3 & 3) * 256 + tid;
        const int b = b3 >> 2;
        const float* qb = q + b * DQ;
        const float* w2 = W2 + u;
        float a0 = 0.0f, a1 = 0.0f, a2 = 0.0f, a3 = 0.0f;
#pragma unroll 8
        for (int d = 0; d < DQ; d += 4) {
            a0 = fmaf(qb[d],     w2[(size_t)d * UN],           a0);
            a1 = fmaf(qb[d + 1], w2[(size_t)(d + 1) * UN],     a1);
            a2 = fmaf(qb[d + 2], w2[(size_t)(d + 2) * UN],     a2);
            a3 = fmaf(qb[d + 3], w2[(size_t)(d + 3) * UN],     a3);
        }
        g_projq[b * UN + u] = b2[u] + ((a0 + a1) + (a2 + a3));
    }
}

// ---------------------------------------------------------------------------
// score: fused values-split + fp16 HMMA GEMM.
// bid < 512: converter CTA (bx=0, by=bid); bid >= 512: consumer.
// ---------------------------------------------------------------------------
__global__ __launch_bounds__(288, 2) void score_kernel(
    const float* __restrict__ vsrc,
    const float* __restrict__ b1g, const float* __restrict__ Vv) {

    extern __shared__ char smem[];
    const uint32_t sb    = smem_u32(smem);
    const uint32_t FULLB = sb;
    const uint32_t EMPTB = sb + 24;
    const uint32_t SDATA = sb + 1024;

    const int tid = threadIdx.x, wid = tid >> 5, lane = tid & 31;
    const int bid = blockIdx.x;
    int bx, by;
    if (bid < NRB) { bx = 0; by = bid; }
    else { const int x = bid - NRB; by = x / 7; bx = 1 + x % 7; }
    const int u0   = bx * BN;
    const int row0 = by * BM;
    const int b    = row0 >> 11;
    const int warp_m = wid & 1, warp_n = wid >> 1;

    const unsigned char* gA = g_at + (size_t)by * (NCHUNK * CHUNK_A);
    const unsigned char* gB = g_bt + (size_t)bx * (NCHUNK * CHUNK_B);

    if (tid == 0) {
#pragma unroll
        for (int st = 0; st < NSTAGE; ++st) {
            MBARRIER_INIT(FULLB + st * 8, 1);
            MBARRIER_INIT(EMPTB + st * 8, 8);
        }
    }
    __syncthreads();

    if (bx == 0) {
        // -------- convert own row-block: fp32 values -> swizzled fp16 -------
        if (wid < 8) {
            const float* src = vsrc + (size_t)by * (BM * DV);
            unsigned char* dstb = g_at + (size_t)by * (NCHUNK * CHUNK_A);
#pragma unroll 4
            for (int it = 0; it < 64; ++it) {
                const int il = it * 2048 + tid * 8;
                const float4 x0 = *(const float4*)(src + il);
                const float4 x1 = *(const float4*)(src + il + 4);
                const int row = il >> 10, col = il & 1023;
                const int ch = col >> 5, ci = col & 31;
                const int sw = (ci >> 3) ^ ((row >> 1) & 3);
                unsigned char* p = dstb + (size_t)ch * CHUNK_A + row * 64 + sw * 16;
                __half2 a0 = __halves2half2(__float2half_rn(x0.x), __float2half_rn(x0.y));
                __half2 a1 = __halves2half2(__float2half_rn(x0.z), __float2half_rn(x0.w));
                __half2 a2 = __halves2half2(__float2half_rn(x1.x), __float2half_rn(x1.y));
                __half2 a3 = __halves2half2(__float2half_rn(x1.z), __float2half_rn(x1.w));
                uint4 out;
                out.x = *(uint32_t*)&a0; out.y = *(uint32_t*)&a1;
                out.z = *(uint32_t*)&a2; out.w = *(uint32_t*)&a3;
                *(uint4*)p = out;
            }
        }
        __syncthreads();
        if (tid == 0) {
            asm volatile("membar.gl;" ::: "memory");
            asm volatile("st.release.gpu.global.b32 [%0], %1;"
                         :: "l"(g_flag + by), "r"(1) : "memory");
        }
    }

    if (wid == 8) {
        // ---------------- producer warp -------------------------------------
        if (lane == 0) {
            if (bx != 0) {
                int f;
                do {
                    asm volatile("ld.acquire.gpu.global.b32 %0, [%1];"
                                 : "=r"(f) : "l"(g_flag + by) : "memory");
                    if (!f) __nanosleep(256);
                } while (!f);
            }
            FENCE_PROXY_ASYNC_GEN();
            int st = 0, r = 0;
            for (int t = 0; t < NSTEP; ++t) {
                if (t >= NSTAGE) MBARRIER_WAIT_RELAXED(EMPTB + st * 8, (r - 1) & 1);
                const uint32_t dst = SDATA + st * STAGE_BYTES;
                MBARRIER_EXPECT_TX(FULLB + st * 8, STAGE_BYTES);
                cp_bulk(dst,         gA + (size_t)t * 16384, 16384, FULLB + st * 8);
                cp_bulk(dst + 16384, gB + (size_t)t * 16384, 16384, FULLB + st * 8);
                if (++st == NSTAGE) { st = 0; ++r; }
            }
        }
    } else {
        // ---------------- compute warps -------------------------------------
        const int lr = lane & 15, lh = lane >> 4;
        uint32_t aoff[4], boff[2];
#pragma unroll
        for (int mt = 0; mt < 4; ++mt)
            aoff[mt] = sw64_off(warp_m * 64 + mt * 16 + lr, lh);
#pragma unroll
        for (int bt = 0; bt < 2; ++bt)
            boff[bt] = sw64_off(warp_n * 32 + bt * 16 + lr, lh);

        float acc[4][4][4];
#pragma unroll
        for (int i = 0; i < 4; ++i)
#pragma unroll
            for (int j = 0; j < 4; ++j)
#pragma unroll
                for (int k = 0; k < 4; ++k) acc[i][j][k] = 0.0f;

        int st = 0, rnd = 0;
        for (int s = 0; s < NSTEP; ++s) {
            const uint32_t sb_cp = SDATA + st * STAGE_BYTES;
            MBARRIER_WAIT(FULLB + st * 8, rnd & 1);

            uint32_t a[2][4][4], bh[2][4];
#pragma unroll
            for (int mt = 0; mt < 4; ++mt)
                LDSM_X4(a[0][mt], sb_cp + aoff[mt]);

#pragma unroll
            for (int k = 0; k < 4; ++k) {
                const int cur = k & 1, nxt = cur ^ 1;
                const uint32_t sub = (k >> 1) * 8192;
                const uint32_t kx  = (k & 1) << 5;
                const uint32_t abase = sb_cp + sub;
#pragma unroll
                for (int bt = 0; bt < 2; ++bt)
                    LDSM_X4(bh[bt], abase + 16384 + (boff[bt] ^ kx));
                if (k < 3) {
                    const int k2 = k + 1;
                    const uint32_t sub2 = (k2 >> 1) * 8192;
                    const uint32_t kx2  = (k2 & 1) << 5;
#pragma unroll
                    for (int mt = 0; mt < 4; ++mt)
                        LDSM_X4(a[nxt][mt], sb_cp + sub2 + (aoff[mt] ^ kx2));
                } else {
                    if (lane == 0) MBARRIER_ARRIVE(EMPTB + st * 8);
                }
#pragma unroll
                for (int mt = 0; mt < 4; ++mt)
#pragma unroll
                    for (int nt = 0; nt < 4; ++nt)
                        MMA16816(acc[mt][nt], a[cur][mt],
                                 bh[nt >> 1][nt & 1], bh[nt >> 1][(nt & 1) + 2]);
            }
            if (++st == NSTAGE) { st = 0; ++rnd; }
        }

        __syncthreads();   // joins producer sync below

        // ---------------- fused epilogue (MUFU tanh) ------------------------
        float tb[8], tv[8];
#pragma unroll
        for (int nt = 0; nt < 4; ++nt)
#pragma unroll
            for (int par = 0; par < 2; ++par) {
                const int u = u0 + warp_n * 32 + nt * 8 + (lane & 3) * 2 + par;
                tb[nt * 2 + par] = b1g[u] + g_projq[b * UN + u];
                tv[nt * 2 + par] = Vv[u];
            }

        float* red = (float*)(smem + 1024);
#pragma unroll
        for (int mt = 0; mt < 4; ++mt) {
            float s0 = 0.0f, s1 = 0.0f;
#pragma unroll
            for (int nt = 0; nt < 4; ++nt)
#pragma unroll
                for (int par = 0; par < 2; ++par) {
                    const int j = nt * 2 + par;
                    s0 = fmaf(tanh_mufu(acc[mt][nt][par]     + tb[j]), tv[j], s0);
                    s1 = fmaf(tanh_mufu(acc[mt][nt][2 + par] + tb[j]), tv[j], s1);
                }
            s0 += __shfl_xor_sync(0xffffffff, s0, 1);
            s0 += __shfl_xor_sync(0xffffffff, s0, 2);
            s1 += __shfl_xor_sync(0xffffffff, s1, 1);
            s1 += __shfl_xor_sync(0xffffffff, s1, 2);
            if ((lane & 3) == 0) {
                const int r = warp_m * 64 + mt * 16 + (lane >> 2);
                red[r * 4 + warp_n]       = s0;
                red[(r + 8) * 4 + warp_n] = s1;
            }
        }
    }
    if (wid == 8) __syncthreads();   // producer joins first barrier
    __syncthreads();                  // red[] complete
    if (tid < 128) {
        float* red = (float*)(smem + 1024);
        const float s = (red[tid * 4 + 0] + red[tid * 4 + 1]) +
                        (red[tid * 4 + 2] + red[tid * 4 + 3]);
        g_spart[(size_t)(row0 + tid) * 8 + bx] = s;
    }
}

// ---------------------------------------------------------------------------
// softmax phase 1: fold 8 partials, per-chunk max + expsum. grid(32, 8) x 256
// ---------------------------------------------------------------------------
__global__ void softmax_part_kernel() {
    const int b = blockIdx.x, chk = blockIdx.y, tid = threadIdx.x;
    const int row = b * SEQ + chk * 256 + tid;
    const float* p = g_spart + (size_t)row * 8;
    const float v = ((p[0] + p[1]) + (p[2] + p[3])) + ((p[4] + p[5]) + (p[6] + p[7]));
    g_score[row] = v;
    __shared__ float sm[256];
    sm[tid] = v; __syncthreads();
    for (int s = 128; s > 0; s >>= 1) {
        if (tid < s) sm[tid] = fmaxf(sm[tid], sm[tid + s]);
        __syncthreads();
    }
    const float m = sm[0]; __syncthreads();
    sm[tid] = __expf(v - m); __syncthreads();
    for (int s = 128; s > 0; s >>= 1) {
        if (tid < s) sm[tid] += sm[tid + s];
        __syncthreads();
    }
    if (tid == 0) {
        g_stats[(b * 8 + chk) * 2]     = m;
        g_stats[(b * 8 + chk) * 2 + 1] = sm[0];
    }
}

// ---------------------------------------------------------------------------
// context partial (fused softmax finalize)
// ---------------------------------------------------------------------------
__global__ void ctx_part_kernel(float* __restrict__ out_w) {
    __shared__ float ws[32];
    __shared__ float part[128 * 8];
    const int sc = blockIdx.x, b = blockIdx.y, tid = threadIdx.x;

    float M = -1e30f;
#pragma unroll
    for (int c = 0; c < 8; ++c) M = fmaxf(M, g_stats[(b * 8 + c) * 2]);
    float S = 0.0f;
#pragma unroll
    for (int c = 0; c < 8; ++c)
        S += g_stats[(b * 8 + c) * 2 + 1] * __expf(g_stats[(b * 8 + c) * 2] - M);
    const float inv = 1.0f / S;

    if (tid < 32) {
        const int row = b * SEQ + sc * 32 + tid;
        const float wv = __expf(g_score[row] - M) * inv;
        ws[tid] = wv;
        out_w[row] = wv;
    }
    __syncthreads();

    const int g  = tid & 127;
    const int h  = tid >> 7;
    const int ch = g >> 2;
    const int c  = g & 3;
    const int row_base = b * SEQ + sc * 32;
    const int rb = row_base >> 7;
    const int r0 = (row_base & 127) + h * 16;
    const unsigned char* tile = g_at + ((size_t)(rb * NCHUNK + ch) * CHUNK_A);

    float acc[8];
#pragma unroll
    for (int k = 0; k < 8; ++k) acc[k] = 0.0f;
#pragma unroll
    for (int j = 0; j < 16; ++j) {
        const int r = r0 + j;
        const uint4 pk = *(const uint4*)(tile + r * 64 + ((c ^ ((r >> 1) & 3)) << 4));
        const __half2 p0 = *(const __half2*)&pk.x;
        const __half2 p1 = *(const __half2*)&pk.y;
        const __half2 p2 = *(const __half2*)&pk.z;
        const __half2 p3 = *(const __half2*)&pk.w;
        const float x = ws[h * 16 + j];
        acc[0] = fmaf(x, __low2float(p0),  acc[0]);
        acc[1] = fmaf(x, __high2float(p0), acc[1]);
        acc[2] = fmaf(x, __low2float(p1),  acc[2]);
        acc[3] = fmaf(x, __high2float(p1), acc[3]);
        acc[4] = fmaf(x, __low2float(p2),  acc[4]);
        acc[5] = fmaf(x, __high2float(p2), acc[5]);
        acc[6] = fmaf(x, __low2float(p3),  acc[6]);
        acc[7] = fmaf(x, __high2float(p3), acc[7]);
    }
    if (h == 1) {
#pragma unroll
        for (int k = 0; k < 8; ++k) part[g * 8 + k] = acc[k];
    }
    __syncthreads();
    if (h == 0) {
        float* dst = g_cpart + (size_t)(sc * BATCH + b) * DV + g * 8;
        float4 o0, o1;
        o0.x = acc[0] + part[g * 8 + 0]; o0.y = acc[1] + part[g * 8 + 1];
        o0.z = acc[2] + part[g * 8 + 2]; o0.w = acc[3] + part[g * 8 + 3];
        o1.x = acc[4] + part[g * 8 + 4]; o1.y = acc[5] + part[g * 8 + 5];
        o1.z = acc[6] + part[g * 8 + 6]; o1.w = acc[7] + part[g * 8 + 7];
        *(float4*)dst       = o0;
        *(float4*)(dst + 4) = o1;
    }
}

__global__ void ctx_reduce_kernel(float* __restrict__ out_c) {
    const int idx = blockIdx.x * 256 + threadIdx.x;
    const int bb = idx >> 10, dd = idx & 1023;
    float s = 0.0f;
#pragma unroll 8
    for (int c = 0; c < NCTX; ++c)
        s += g_cpart[(size_t)(c * BATCH + bb) * DV + dd];
    out_c[idx] = s;
}

// ---------------------------------------------------------------------------
extern "C" void kernel_launch(void* const* d_in, const int* in_sizes, int n_in,
                              void* d_out, int out_size) {
    const float* query  = (const float*)d_in[0];
    const float* values = (const float*)d_in[1];
    const float* W1     = (const float*)d_in[2];
    const float* b1     = (const float*)d_in[3];
    const float* W2     = (const float*)d_in[4];
    const float* b2     = (const float*)d_in[5];
    const float* Vv     = (const float*)d_in[6];
    // d_in[7] = bV: cancels in softmax.

    float* out_c = (float*)d_out;
    float* out_w = out_c + BATCH * DV;

    static bool attr_set = false;
    if (!attr_set) {
        cudaFuncSetAttribute(score_kernel,
                             cudaFuncAttributeMaxDynamicSharedMemorySize, SMEM_BYTES);
        attr_set = true;
    }

    prep_kernel<<<PREP_BLOCKS, 256>>>(W1, query, W2, b2);
    score_kernel<<<4096, 288, SMEM_BYTES>>>(values, b1, Vv);
    softmax_part_kernel<<<dim3(BATCH, 8), 256>>>();
    ctx_part_kernel<<<dim3(NCTX, BATCH), 256>>>(out_w);
    ctx_reduce_kernel<<<128, 256>>>(out_c);
}